// round 10
// baseline (speedup 1.0000x reference)
#include <cuda_runtime.h>
#include <cuda_fp16.h>
#include <cstdint>
#include <float.h>

#define PQ   8191
#define NDIM 1024
#define LDS  8192

// ---------------- scratch (static device memory, no allocation) ------------
__device__ float  g_S [(size_t)LDS * LDS];      // 8192x8192 fp32 logits
__device__ __half g_sh[(size_t)8192 * 1024];
__device__ __half g_sl[(size_t)8192 * 1024];
__device__ __half g_xh[(size_t)8192 * 1024];
__device__ __half g_xl[(size_t)8192 * 1024];
__device__ __half g_vth[(size_t)1024 * 8192];   // V^T (fp16, single) : [n][k]
__device__ __half g_Ph[(size_t)8192 * 8192];    // probs hi
__device__ __half g_Pl[(size_t)8192 * 8192];    // probs lo

// ---------------- helpers ---------------------------------------------------
__device__ __forceinline__ uint32_t smem_to_u32(const void* p) {
    uint32_t a;
    asm("{ .reg .u64 t; cvta.to.shared.u64 t, %1; cvt.u32.u64 %0, t; }" : "=r"(a) : "l"(p));
    return a;
}
__device__ __forceinline__ void cp16(uint32_t s, const void* g) {
    asm volatile("cp.async.cg.shared.global [%0], [%1], 16;" :: "r"(s), "l"(g));
}
#define CP_COMMIT() asm volatile("cp.async.commit_group;" ::: "memory")
#define CP_WAIT1()  asm volatile("cp.async.wait_group 1;" ::: "memory")

#define LDSM_X4(R, ADDR) \
    asm volatile("ldmatrix.sync.aligned.m8n8.x4.shared.b16 {%0,%1,%2,%3}, [%4];" \
        : "=r"((R)[0]), "=r"((R)[1]), "=r"((R)[2]), "=r"((R)[3]) : "r"(ADDR))
#define LDSM_X2(R, ADDR) \
    asm volatile("ldmatrix.sync.aligned.m8n8.x2.shared.b16 {%0,%1}, [%2];" \
        : "=r"((R)[0]), "=r"((R)[1]) : "r"(ADDR))
#define MMA16816(D, A, B) \
    asm volatile("mma.sync.aligned.m16n8k16.row.col.f32.f16.f16.f32 " \
        "{%0,%1,%2,%3}, {%4,%5,%6,%7}, {%8,%9}, {%0,%1,%2,%3};" \
        : "+f"((D)[0]), "+f"((D)[1]), "+f"((D)[2]), "+f"((D)[3]) \
        : "r"((A)[0]), "r"((A)[1]), "r"((A)[2]), "r"((A)[3]), "r"((B)[0]), "r"((B)[1]))

// XOR-swizzled smem layout for a 128row x 64B tile: conflict-free for
// cp.async 16B stores and ldmatrix (8 rows map to 8 distinct 16B slots).
__device__ __forceinline__ uint32_t sw_off(int row, int chunk) {
    return (uint32_t)(row * 64 + ((chunk ^ ((row >> 1) & 3)) << 4));
}

// ---------------- prep kernels ---------------------------------------------
__global__ void cvt_split(const float* __restrict__ src, __half* __restrict__ hi,
                          __half* __restrict__ lo, size_t nvalid) {
    size_t i = (size_t)blockIdx.x * blockDim.x + threadIdx.x;
    float v = (i < nvalid) ? src[i] : 0.f;
    __half h = __float2half(v);
    hi[i] = h;
    lo[i] = __float2half(v - __half2float(h));
}

// Vt[n][k] = X[k+1][n] for k < 8191, else 0 (single fp16).
__global__ void transpose_half(const float* __restrict__ X) {
    __shared__ float t[32][33];
    int k0 = blockIdx.x * 32, n0 = blockIdx.y * 32;
    int tx = threadIdx.x, ty = threadIdx.y;            // 32 x 8
    for (int i = ty; i < 32; i += 8) {
        int k = k0 + i;
        float v = 0.f;
        if (k < PQ) v = X[(size_t)(k + 1) * NDIM + n0 + tx];
        t[i][tx] = v;
    }
    __syncthreads();
    for (int i = ty; i < 32; i += 8) {
        int n = n0 + i;
        g_vth[(size_t)n * LDS + k0 + tx] = __float2half(t[tx][i]);
    }
}

// ---------------- softmax: g_S row -> g_Ph/g_Pl (fp16 hi/lo) ---------------
__global__ __launch_bounds__(256) void softmax_rows() {
    __shared__ float row[LDS];
    __shared__ float sred[8];
    const int q = blockIdx.x;
    const int tid = threadIdx.x;
    const float* r = g_S + (size_t)q * LDS;

    const float4* r4 = (const float4*)r;
    float4* row4 = (float4*)row;
    for (int i = tid; i < LDS / 4; i += 256) row4[i] = r4[i];
    __syncthreads();
    if (tid == 0) row[PQ] = -1e30f;   // pad key -> prob 0
    __syncthreads();

    float lmax = -FLT_MAX;
    for (int i = tid; i < LDS; i += 256) lmax = fmaxf(lmax, row[i]);
#pragma unroll
    for (int o = 16; o; o >>= 1) lmax = fmaxf(lmax, __shfl_xor_sync(0xffffffffu, lmax, o));
    if ((tid & 31) == 0) sred[tid >> 5] = lmax;
    __syncthreads();
    float m = sred[0];
#pragma unroll
    for (int w = 1; w < 8; w++) m = fmaxf(m, sred[w]);
    __syncthreads();

    float lsum = 0.f;
    for (int i = tid; i < LDS; i += 256) {
        float e = __expf(row[i] - m);
        row[i] = e;
        lsum += e;
    }
#pragma unroll
    for (int o = 16; o; o >>= 1) lsum += __shfl_xor_sync(0xffffffffu, lsum, o);
    if ((tid & 31) == 0) sred[tid >> 5] = lsum;
    __syncthreads();
    float tot = 0.f;
#pragma unroll
    for (int w = 0; w < 8; w++) tot += sred[w];
    const float inv = 1.f / tot;

    __half2* ph2 = (__half2*)(g_Ph + (size_t)q * LDS);
    __half2* pl2 = (__half2*)(g_Pl + (size_t)q * LDS);
    for (int i = tid; i < LDS / 2; i += 256) {
        float p0 = row[2 * i] * inv;
        float p1 = row[2 * i + 1] * inv;
        __half h0 = __float2half(p0), h1 = __float2half(p1);
        ph2[i] = __halves2half2(h0, h1);
        pl2[i] = __halves2half2(__float2half(p0 - __half2float(h0)),
                                __float2half(p1 - __half2float(h1)));
    }
}

// ---------------- split-fp16 HMMA GEMM -------------------------------------
// C[128*by][128*bx] = split(A) @ split(B)^T, K-major operands.
// BM=BN=128, BK=32, 128 threads (4 warps 2x2, warp tile 64x64),
// 3-stage cp.async pipeline (XOR-swizzled smem, no padding), 2 CTAs/SM,
// one __syncthreads per K-iter, loads issued before compute.
// NPASS=3: Ah.Bh + Ah.Bl + Al.Bh   NPASS=2: Ah.Bh + Al.Bh (B single fp16)
#define MATB   8192                      // 128 rows x 64 B, swizzled
#define NSTAGE 3

template <int NPASS>
__global__ __launch_bounds__(128, 2) void mma_gemm(
        const __half* __restrict__ Ah, const __half* __restrict__ Al, size_t lda,
        const __half* __restrict__ Bh, const __half* __restrict__ Bl, size_t ldb,
        float* __restrict__ C, size_t ldc, int K, int out_rows) {
    constexpr int NMAT = (NPASS == 3) ? 4 : 3;   // Ah|Al|Bh|(Bl)
    constexpr int STAGEB = NMAT * MATB;
    extern __shared__ char sm[];
    const uint32_t smb = smem_to_u32(sm);
    const int tid = threadIdx.x, lane = tid & 31, wid = tid >> 5;
    const int wm = wid & 1, wn = wid >> 1;       // 2x2 warp grid, warp tile 64x64
    const size_t arow0 = (size_t)blockIdx.y * 128;
    const size_t brow0 = (size_t)blockIdx.x * 128;

    float acc[4][8][4];
#pragma unroll
    for (int a = 0; a < 4; a++)
#pragma unroll
        for (int b = 0; b < 8; b++)
#pragma unroll
            for (int c = 0; c < 4; c++) acc[a][b][c] = 0.f;

    auto load_stage = [&](int stg, int k0) {
        const uint32_t base = smb + stg * STAGEB;
#pragma unroll
        for (int c = tid; c < 512; c += 128) {        // 128 rows x 4 16B-chunks
            const int row = c >> 2, kc = c & 3;
            const uint32_t so = base + sw_off(row, kc);
            const size_t ga = (arow0 + row) * lda + k0 + kc * 8;
            const size_t gb = (brow0 + row) * ldb + k0 + kc * 8;
            cp16(so,            Ah + ga);
            cp16(so + MATB,     Al + ga);
            cp16(so + 2 * MATB, Bh + gb);
            if (NPASS == 3) cp16(so + 3 * MATB, Bl + gb);
        }
    };

    const int nk = K / 32;
    load_stage(0, 0);  CP_COMMIT();
    load_stage(1, 32); CP_COMMIT();

    for (int it = 0; it < nk; ++it) {
        CP_WAIT1();
        __syncthreads();
        // prefetch stage it+2 into the slot freed after iter it-1
        if (it + 2 < nk) load_stage((it + 2) % NSTAGE, (it + 2) * 32);
        CP_COMMIT();

        const uint32_t base = smb + (it % NSTAGE) * STAGEB;
#pragma unroll
        for (int ks = 0; ks < 2; ks++) {
            const int a_row = wm * 64 + (lane & 15);
            const int a_ch  = ks * 2 + (lane >> 4);
            const int b_row = wn * 64 + (lane & 7);
            const int b_ch  = ks * 2 + ((lane >> 3) & 1);
            uint32_t fa[4][4], bh[8][2], bl[8][2];
            // group 1: ah, bh -> ah.bh
#pragma unroll
            for (int mi = 0; mi < 4; mi++)
                LDSM_X4(fa[mi], base + sw_off(a_row + mi * 16, a_ch));
#pragma unroll
            for (int ni = 0; ni < 8; ni++)
                LDSM_X2(bh[ni], base + 2 * MATB + sw_off(b_row + ni * 8, b_ch));
            if (NPASS == 3) {   // prefetch bl under the hi.hi mma block
#pragma unroll
                for (int ni = 0; ni < 8; ni++)
                    LDSM_X2(bl[ni], base + 3 * MATB + sw_off(b_row + ni * 8, b_ch));
            }
#pragma unroll
            for (int mi = 0; mi < 4; mi++)
#pragma unroll
                for (int ni = 0; ni < 8; ni++) MMA16816(acc[mi][ni], fa[mi], bh[ni]);
            // group 2: ah.bl (NPASS==3)
            if (NPASS == 3) {
#pragma unroll
                for (int mi = 0; mi < 4; mi++)
#pragma unroll
                    for (int ni = 0; ni < 8; ni++) MMA16816(acc[mi][ni], fa[mi], bl[ni]);
            }
            // group 3: overwrite fa <- al, then al.bh
#pragma unroll
            for (int mi = 0; mi < 4; mi++)
                LDSM_X4(fa[mi], base + MATB + sw_off(a_row + mi * 16, a_ch));
#pragma unroll
            for (int mi = 0; mi < 4; mi++)
#pragma unroll
                for (int ni = 0; ni < 8; ni++) MMA16816(acc[mi][ni], fa[mi], bh[ni]);
        }
    }

    // epilogue: direct fp32 stores
#pragma unroll
    for (int mi = 0; mi < 4; mi++) {
        const size_t q0 = arow0 + wm * 64 + mi * 16 + (lane >> 2);
        const size_t q1 = q0 + 8;
#pragma unroll
        for (int ni = 0; ni < 8; ni++) {
            const size_t col = brow0 + wn * 64 + ni * 8 + (lane & 3) * 2;
            if ((int)q0 < out_rows)
                *(float2*)&C[q0 * ldc + col] = make_float2(acc[mi][ni][0], acc[mi][ni][1]);
            if ((int)q1 < out_rows)
                *(float2*)&C[q1 * ldc + col] = make_float2(acc[mi][ni][2], acc[mi][ni][3]);
        }
    }
}

// ---------------- launcher -------------------------------------------------
extern "C" void kernel_launch(void* const* d_in, const int* in_sizes, int n_in,
                              void* d_out, int out_size) {
    const float* X = (const float*)d_in[0];   // (8192, 1024)
    const float* s = (const float*)d_in[1];   // (8191, 1024)
    float* out = (float*)d_out;               // (8191, 1024)

    const int GS3 = NSTAGE * 4 * MATB;        // 98304 B
    const int GS2 = NSTAGE * 3 * MATB;        // 73728 B

    static bool attr_set = false;
    if (!attr_set) {
        cudaFuncSetAttribute(mma_gemm<3>, cudaFuncAttributeMaxDynamicSharedMemorySize, GS3);
        cudaFuncSetAttribute(mma_gemm<2>, cudaFuncAttributeMaxDynamicSharedMemorySize, GS2);
        attr_set = true;
    }

    void *p_sh, *p_sl, *p_xh, *p_xl, *p_vth, *p_S, *p_Ph, *p_Pl;
    cudaGetSymbolAddress(&p_sh, g_sh);   cudaGetSymbolAddress(&p_sl, g_sl);
    cudaGetSymbolAddress(&p_xh, g_xh);   cudaGetSymbolAddress(&p_xl, g_xl);
    cudaGetSymbolAddress(&p_vth, g_vth);
    cudaGetSymbolAddress(&p_S, g_S);
    cudaGetSymbolAddress(&p_Ph, g_Ph);   cudaGetSymbolAddress(&p_Pl, g_Pl);

    const size_t NE = (size_t)8192 * 1024;

    cvt_split<<<NE / 256, 256>>>(s, (__half*)p_sh, (__half*)p_sl, (size_t)PQ * NDIM);
    cvt_split<<<NE / 256, 256>>>(X, (__half*)p_xh, (__half*)p_xl, NE);
    transpose_half<<<dim3(256, 32), dim3(32, 8)>>>(X);

    // K1: S = s @ X^T   (M=8192 pad, N=8192, K=1024), 3-pass split
    mma_gemm<3><<<dim3(64, 64), 128, GS3>>>(
        (const __half*)p_sh, (const __half*)p_sl, (size_t)NDIM,
        (const __half*)p_xh, (const __half*)p_xl, (size_t)NDIM,
        (float*)p_S, (size_t)LDS, NDIM, 8192);

    // K2: softmax rows -> P (fp16 hi/lo), pad col = 0
    softmax_rows<<<PQ, 256>>>();

    // K3: out = P @ V   (M=8192 pad, N=1024, K=8192), 2-pass (V single fp16)
    mma_gemm<2><<<dim3(8, 64), 128, GS2>>>(
        (const __half*)p_Ph, (const __half*)p_Pl, (size_t)LDS,
        (const __half*)p_vth, (const __half*)nullptr, (size_t)LDS,
        out, (size_t)NDIM, LDS, PQ);
}

// round 12
// speedup vs baseline: 4.6389x; 4.6389x over previous
#include <cuda_runtime.h>
#include <cuda_fp16.h>
#include <cstdint>
#include <float.h>

#define PQ   8191
#define NDIM 1024
#define LDS  8192
#define MARGIN 25.0f
#define MAXSEL 2048

// ---------------- scratch (static device memory, no allocation) ------------
__device__ __half g_S [(size_t)LDS * LDS];      // 8192x8192 fp16 approx logits
__device__ __half g_sh[(size_t)8192 * 1024];    // s  in fp16 (row 8191 zero)
__device__ __half g_xh[(size_t)8192 * 1024];    // X  in fp16

// ---------------- helpers ---------------------------------------------------
__device__ __forceinline__ uint32_t smem_to_u32(const void* p) {
    uint32_t a;
    asm("{ .reg .u64 t; cvta.to.shared.u64 t, %1; cvt.u32.u64 %0, t; }" : "=r"(a) : "l"(p));
    return a;
}
__device__ __forceinline__ void cp16(uint32_t s, const void* g) {
    asm volatile("cp.async.cg.shared.global [%0], [%1], 16;" :: "r"(s), "l"(g));
}
#define CP_COMMIT() asm volatile("cp.async.commit_group;" ::: "memory")
#define CP_WAIT1()  asm volatile("cp.async.wait_group 1;" ::: "memory")

#define LDSM_X4(R, ADDR) \
    asm volatile("ldmatrix.sync.aligned.m8n8.x4.shared.b16 {%0,%1,%2,%3}, [%4];" \
        : "=r"((R)[0]), "=r"((R)[1]), "=r"((R)[2]), "=r"((R)[3]) : "r"(ADDR))
#define LDSM_X2(R, ADDR) \
    asm volatile("ldmatrix.sync.aligned.m8n8.x2.shared.b16 {%0,%1}, [%2];" \
        : "=r"((R)[0]), "=r"((R)[1]) : "r"(ADDR))
#define MMA16816(D, A, B) \
    asm volatile("mma.sync.aligned.m16n8k16.row.col.f32.f16.f16.f32 " \
        "{%0,%1,%2,%3}, {%4,%5,%6,%7}, {%8,%9}, {%0,%1,%2,%3};" \
        : "+f"((D)[0]), "+f"((D)[1]), "+f"((D)[2]), "+f"((D)[3]) \
        : "r"((A)[0]), "r"((A)[1]), "r"((A)[2]), "r"((A)[3]), "r"((B)[0]), "r"((B)[1]))

// ---------------- prep: fp32 -> fp16 ---------------------------------------
__global__ void cvt_half(const float* __restrict__ src, __half* __restrict__ dst,
                         size_t nvalid) {
    size_t i = (size_t)blockIdx.x * blockDim.x + threadIdx.x;
    float v = (i < nvalid) ? src[i] : 0.f;
    dst[i] = __float2half(v);
}

// ---------------- Phase A: 1-pass fp16 QK GEMM -----------------------------
// S[128*by : +128][128*bx : +128] = sh @ xh^T (approx logits, fp16 out).
// BM=BN=128, BK=32, 128 threads (2x2 warps, warp tile 64x64),
// 2-stage cp.async pipeline, padded 80B rows (round-6 winner schedule).
#define ROWB   80
#define MATB   (128 * ROWB)              // 10240 B
#define STAGEB (2 * MATB)                // Ah | Bh
#define GSMEM  (2 * STAGEB)              // 40960 B

__global__ __launch_bounds__(128, 2) void qk_gemm(
        const __half* __restrict__ Ah, const __half* __restrict__ Bh) {
    extern __shared__ char sm[];
    const uint32_t smb = smem_to_u32(sm);
    const int tid = threadIdx.x, lane = tid & 31, wid = tid >> 5;
    const int wm = wid & 1, wn = wid >> 1;
    const size_t arow0 = (size_t)blockIdx.y * 128;
    const size_t brow0 = (size_t)blockIdx.x * 128;

    float acc[4][8][4];
#pragma unroll
    for (int a = 0; a < 4; a++)
#pragma unroll
        for (int b = 0; b < 8; b++)
#pragma unroll
            for (int c = 0; c < 4; c++) acc[a][b][c] = 0.f;

    auto load_stage = [&](int stg, int k0) {
        const uint32_t base = smb + stg * STAGEB;
#pragma unroll
        for (int c = tid; c < 512; c += 128) {        // 128 rows x 4 16B-chunks
            const int row = c >> 2, kc = c & 3;
            const uint32_t so = base + row * ROWB + kc * 16;
            cp16(so,        Ah + (arow0 + row) * NDIM + k0 + kc * 8);
            cp16(so + MATB, Bh + (brow0 + row) * NDIM + k0 + kc * 8);
        }
    };

    const int nk = NDIM / 32;
    load_stage(0, 0);  CP_COMMIT();
    load_stage(1, 32); CP_COMMIT();

    for (int it = 0; it < nk; ++it) {
        CP_WAIT1();
        __syncthreads();

        const uint32_t base = smb + (it & 1) * STAGEB;
#pragma unroll
        for (int ks = 0; ks < 2; ks++) {
            const int k0 = ks * 16;
            const uint32_t a_off = (uint32_t)((wm * 64 + (lane & 15)) * ROWB + (k0 + (lane >> 4) * 8) * 2);
            const uint32_t b_off = (uint32_t)((wn * 64 + (lane & 7)) * ROWB + (k0 + ((lane >> 3) & 1) * 8) * 2);
            uint32_t fa[4][4], fb[8][2];
#pragma unroll
            for (int mi = 0; mi < 4; mi++) LDSM_X4(fa[mi], base + a_off + mi * 16 * ROWB);
#pragma unroll
            for (int ni = 0; ni < 8; ni++) LDSM_X2(fb[ni], base + MATB + b_off + ni * 8 * ROWB);
#pragma unroll
            for (int mi = 0; mi < 4; mi++)
#pragma unroll
                for (int ni = 0; ni < 8; ni++) MMA16816(acc[mi][ni], fa[mi], fb[ni]);
        }
        __syncthreads();

        if (it + 2 < nk) load_stage(it & 1, (it + 2) * 32);
        CP_COMMIT();
    }

    // epilogue: fp16 stores (half2 per fragment row-half)
#pragma unroll
    for (int mi = 0; mi < 4; mi++) {
        const size_t q0 = arow0 + wm * 64 + mi * 16 + (lane >> 2);
        const size_t q1 = q0 + 8;
#pragma unroll
        for (int ni = 0; ni < 8; ni++) {
            const size_t col = brow0 + wn * 64 + ni * 8 + (lane & 3) * 2;
            *(__half2*)&g_S[q0 * LDS + col] = __floats2half2_rn(acc[mi][ni][0], acc[mi][ni][1]);
            *(__half2*)&g_S[q1 * LDS + col] = __floats2half2_rn(acc[mi][ni][2], acc[mi][ni][3]);
        }
    }
}

// ---------------- Phase B: select + exact softmax + sparse PV --------------
// One block per query row. Approx logits select candidates (margin covers the
// worst-case fp16 GEMM error ~0.7); selected logits recomputed exactly in
// fp32; softmax over selected; output = sum p_k * X[k+1].
__global__ __launch_bounds__(256) void sparse_out(const float* __restrict__ X,
                                                  const float* __restrict__ s,
                                                  float* __restrict__ out) {
    __shared__ float s_srow[NDIM];
    __shared__ int   s_idx[MAXSEL];
    __shared__ float s_val[MAXSEL];
    __shared__ float s_red[8];
    __shared__ int   s_cnt;
    __shared__ float s_bcast[2];

    const int q = blockIdx.x;
    const int tid = threadIdx.x, lane = tid & 31, wid = tid >> 5;
    const __half* Sr = g_S + (size_t)q * LDS;

    // load s[q] into smem (fp32)
    const float4* srow4 = (const float4*)(s + (size_t)q * NDIM);
    for (int i = tid; i < NDIM / 4; i += 256) ((float4*)s_srow)[i] = srow4[i];
    if (tid == 0) s_cnt = 0;

    // pass 1: approx row max (keys 0..PQ-1 only)
    float lmax = -FLT_MAX;
    for (int k = tid; k < PQ; k += 256) lmax = fmaxf(lmax, __half2float(Sr[k]));
#pragma unroll
    for (int o = 16; o; o >>= 1) lmax = fmaxf(lmax, __shfl_xor_sync(0xffffffffu, lmax, o));
    if (lane == 0) s_red[wid] = lmax;
    __syncthreads();
    if (tid == 0) {
        float m = s_red[0];
#pragma unroll
        for (int w = 1; w < 8; w++) m = fmaxf(m, s_red[w]);
        s_bcast[0] = m;
    }
    __syncthreads();
    const float thr = s_bcast[0] - MARGIN;

    // pass 2: select candidates
    for (int k = tid; k < PQ; k += 256) {
        if (__half2float(Sr[k]) >= thr) {
            int p = atomicAdd(&s_cnt, 1);
            if (p < MAXSEL) s_idx[p] = k;
        }
    }
    __syncthreads();
    const int cnt = min(s_cnt, MAXSEL);

    // exact fp32 logits for selected keys: one warp per key (round-robin)
    for (int j = wid; j < cnt; j += 8) {
        const float* xr = X + (size_t)s_idx[j] * NDIM;
        float a = 0.f;
        for (int i = lane; i < NDIM; i += 32) a += s_srow[i] * xr[i];
#pragma unroll
        for (int o = 16; o; o >>= 1) a += __shfl_xor_sync(0xffffffffu, a, o);
        if (lane == 0) s_val[j] = a;
    }
    __syncthreads();

    // softmax over the cnt exact logits (warp 0)
    if (wid == 0) {
        float m = -FLT_MAX;
        for (int j = lane; j < cnt; j += 32) m = fmaxf(m, s_val[j]);
#pragma unroll
        for (int o = 16; o; o >>= 1) m = fmaxf(m, __shfl_xor_sync(0xffffffffu, m, o));
        float sum = 0.f;
        for (int j = lane; j < cnt; j += 32) {
            float e = __expf(s_val[j] - m);
            s_val[j] = e;
            sum += e;
        }
#pragma unroll
        for (int o = 16; o; o >>= 1) sum += __shfl_xor_sync(0xffffffffu, sum, o);
        if (lane == 0) s_bcast[1] = 1.f / sum;
    }
    __syncthreads();
    const float inv = s_bcast[1];

    // output row: out[q] = sum_j p_j * X[idx_j + 1]; 256 threads x float4
    float4 o = make_float4(0.f, 0.f, 0.f, 0.f);
    for (int j = 0; j < cnt; j++) {
        const float p = s_val[j] * inv;
        const float4 v = ((const float4*)(X + (size_t)(s_idx[j] + 1) * NDIM))[tid];
        o.x += p * v.x; o.y += p * v.y; o.z += p * v.z; o.w += p * v.w;
    }
    ((float4*)(out + (size_t)q * NDIM))[tid] = o;
}

// ---------------- launcher -------------------------------------------------
extern "C" void kernel_launch(void* const* d_in, const int* in_sizes, int n_in,
                              void* d_out, int out_size) {
    const float* X = (const float*)d_in[0];   // (8192, 1024)
    const float* s = (const float*)d_in[1];   // (8191, 1024)
    float* out = (float*)d_out;               // (8191, 1024)

    static bool attr_set = false;
    if (!attr_set) {
        cudaFuncSetAttribute(qk_gemm, cudaFuncAttributeMaxDynamicSharedMemorySize, GSMEM);
        attr_set = true;
    }

    void *p_sh, *p_xh;
    cudaGetSymbolAddress(&p_sh, g_sh);
    cudaGetSymbolAddress(&p_xh, g_xh);

    const size_t NE = (size_t)8192 * 1024;

    cvt_half<<<NE / 256, 256>>>(s, (__half*)p_sh, (size_t)PQ * NDIM);
    cvt_half<<<NE / 256, 256>>>(X, (__half*)p_xh, NE);

    // Phase A: approx logits S = s @ X^T  (fp16 in, fp16 out)
    qk_gemm<<<dim3(64, 64), 128, GSMEM>>>((const __half*)p_sh, (const __half*)p_xh);

    // Phase B: select + exact softmax + sparse PV
    sparse_out<<<PQ, 256>>>(X, s, out);
}